// round 4
// baseline (speedup 1.0000x reference)
#include <cuda_runtime.h>
#include <cstdint>
#include <cstddef>

// ---------------------------------------------------------------------------
// BlobStore: top-k Gaussian-blob rendering.
//   Pass P: per-blob precompute  (iv, -2*mu*iv) transposed + bias c[n]
//   Pass S: coarse key[b,n] = mahal - 2*tau*ln(alpha)  (f32x2 packed FMA)
//   Pass T: exact per-query top-64 candidate superset (packed u64, determ.)
//   Pass R: reference-bit-replica fp32 rescore of 64 cands -> top-16 by
//           (score desc, idx asc), then compositing + feature blend.
// ---------------------------------------------------------------------------

#define DS     64          // d_s
#define QT     16          // queries per CTA in scoring pass
#define KTOP   16          // k
#define MCAND  64          // refined candidate superset size
#define NCHUNK 16          // blob chunks in scoring grid
#define TPB    256
#define MAXB   1024
#define MAXN   131072

// Scratch (static __device__ — no allocation anywhere)
__device__ float2             g_ivwT[(size_t)DS * MAXN];      // 64 MB, [d][n] = (iv, -2*mu*iv)
__device__ float              g_c[MAXN];                       // m2 - 2*tau*ln(alpha)
__device__ float              g_keys[(size_t)MAXB * MAXN];     // 512 MB, [b][n]
__device__ unsigned long long g_cand[MAXB * MCAND];            // coarse top-64 (key,idx)

// ---- helpers ---------------------------------------------------------------

__device__ __forceinline__ unsigned long long f2u(float2 v) {
    unsigned long long u;
    asm("mov.b64 %0, {%1, %2};" : "=l"(u) : "f"(v.x), "f"(v.y));
    return u;
}
__device__ __forceinline__ float2 u2f(unsigned long long u) {
    float2 v;
    asm("mov.b64 {%0, %1}, %2;" : "=f"(v.x), "=f"(v.y) : "l"(u));
    return v;
}
// packed fp32x2 FMA: d.lo += a.lo*b.lo ; d.hi += a.hi*b.hi
__device__ __forceinline__ void ffma2(unsigned long long& d,
                                      unsigned long long a, unsigned long long b) {
    asm("fma.rn.f32x2 %0, %1, %2, %0;" : "+l"(d) : "l"(a), "l"(b));
}

// order-preserving float->u32
__device__ __forceinline__ unsigned ordu(float f) {
    unsigned u = __float_as_uint(f);
    return (u & 0x80000000u) ? ~u : (u | 0x80000000u);
}
// ascending u64 == ascending key (smaller better); ties -> lowest index
__device__ __forceinline__ unsigned long long packkey(float f, int idx) {
    return ((unsigned long long)ordu(f) << 32) | (unsigned)idx;
}
// ascending u64 == DESCENDING score; ties -> lowest index (matches lax.top_k)
__device__ __forceinline__ unsigned long long packdesc(float f, int idx) {
    return ((unsigned long long)(~ordu(f)) << 32) | (unsigned)idx;
}

// branch-free sorted insert into ascending arr[0..15]
__device__ __forceinline__ void ins16(unsigned long long* arr, unsigned long long v) {
#pragma unroll
    for (int s = 0; s < KTOP; s++) {
        unsigned long long mn = (v < arr[s]) ? v : arr[s];
        unsigned long long mx = (v < arr[s]) ? arr[s] : v;
        arr[s] = mn;
        v = mx;
    }
}

// ---- Pass P: per-blob precompute ------------------------------------------
__global__ void __launch_bounds__(TPB) prep_kernel(
    const float* __restrict__ mu, const float* __restrict__ log_var,
    const float* __restrict__ raw_alpha, const float* __restrict__ log_tau, int N)
{
    __shared__ float2 tile[32][DS + 1];
    __shared__ float  spart[TPB];
    const int n0  = blockIdx.x * 32;
    const int tid = threadIdx.x;
    const int nl  = tid >> 3;      // local blob 0..31
    const int dg  = tid & 7;       // dim-group 0..7 (8 dims each)
    const int n   = n0 + nl;

    float part = 0.f;
#pragma unroll
    for (int i = 0; i < 8; i++) {
        int   d  = dg * 8 + i;
        float m  = mu[(size_t)n * DS + d];
        float lv = log_var[(size_t)n * DS + d];
        float iv = expf(-lv);
        part += m * m * iv;
        tile[nl][d] = make_float2(iv, -2.f * m * iv);
    }
    spart[tid] = part;
    __syncthreads();

    for (int i = tid; i < 32 * DS; i += TPB) {
        int d  = i >> 5;
        int nn = i & 31;
        g_ivwT[(size_t)d * N + n0 + nn] = tile[nn][d];
    }
    if (tid < 32) {
        float s = 0.f;
#pragma unroll
        for (int j = 0; j < 8; j++) s += spart[tid * 8 + j];   // fixed order
        float tau   = expf(log_tau[0]);
        float ra    = raw_alpha[n0 + tid];
        float alpha = 1.f / (1.f + expf(-ra));
        g_c[n0 + tid] = s - 2.f * tau * logf(alpha);
    }
}

// ---- Pass S: coarse scoring (key matrix) ----------------------------------
// Grid: (NCHUNK, B/QT). Each thread: 2 adjacent blobs x 16 queries.
__global__ void __launch_bounds__(TPB, 2) score_kernel(
    const float* __restrict__ query, int N)
{
    __shared__ unsigned long long sX[DS * QT];   // (q^2, q) per (d, q)
    const int q0 = blockIdx.y * QT;

    for (int i = threadIdx.x; i < DS * QT; i += TPB) {
        int   d = i >> 4;
        int   q = i & 15;
        float v = query[(size_t)(q0 + q) * DS + d];
        sX[d * QT + q] = f2u(make_float2(v * v, v));
    }
    __syncthreads();

    const int chunk = N / NCHUNK;
    const int base0 = blockIdx.x * chunk;
    const int iters = chunk / (2 * TPB);

    for (int it = 0; it < iters; ++it) {
        const int n0 = base0 + it * 2 * TPB + 2 * threadIdx.x;

        unsigned long long acc[QT][2];
#pragma unroll
        for (int q = 0; q < QT; q++) { acc[q][0] = 0ull; acc[q][1] = 0ull; }

#pragma unroll 4
        for (int d = 0; d < DS; ++d) {
            const float4 wv = __ldg(reinterpret_cast<const float4*>(
                &g_ivwT[(size_t)d * N + n0]));
            const unsigned long long b0 = f2u(make_float2(wv.x, wv.y));
            const unsigned long long b1 = f2u(make_float2(wv.z, wv.w));
#pragma unroll
            for (int q = 0; q < QT; q++) {
                unsigned long long a = sX[d * QT + q];
                ffma2(acc[q][0], a, b0);
                ffma2(acc[q][1], a, b1);
            }
        }

        const float2 cp = *reinterpret_cast<const float2*>(&g_c[n0]);
#pragma unroll
        for (int q = 0; q < QT; q++) {
            float2 a0 = u2f(acc[q][0]);
            float2 a1 = u2f(acc[q][1]);
            float2 kv = make_float2(a0.x + a0.y + cp.x, a1.x + a1.y + cp.y);
            __stcs(reinterpret_cast<float2*>(&g_keys[(size_t)(q0 + q) * N + n0]), kv);
        }
    }
}

// ---- Pass T: per-query top-64 candidate superset --------------------------
// Per-thread exact top-16 over a 512-elem slice; 64 rounds of deterministic
// block min-extraction. (Union holds the global top-64 unless one slice owns
// >16 of them — probability ~1e-25 for random placement.)
__global__ void __launch_bounds__(TPB) topk_kernel(int N)
{
    __shared__ unsigned long long cand[KTOP][TPB];
    __shared__ unsigned long long red[TPB];

    const int q   = blockIdx.x;
    const int tid = threadIdx.x;
    const float4* kp = reinterpret_cast<const float4*>(&g_keys[(size_t)q * N]);

    unsigned long long arr[KTOP];
#pragma unroll
    for (int s = 0; s < KTOP; s++) arr[s] = ~0ull;

    const int n4 = N >> 2;
    for (int i = tid; i < n4; i += TPB) {
        float4 v = __ldcs(&kp[i]);
        int bi = i << 2;
        unsigned long long p;
        p = packkey(v.x, bi + 0); if (p < arr[KTOP - 1]) ins16(arr, p);
        p = packkey(v.y, bi + 1); if (p < arr[KTOP - 1]) ins16(arr, p);
        p = packkey(v.z, bi + 2); if (p < arr[KTOP - 1]) ins16(arr, p);
        p = packkey(v.w, bi + 3); if (p < arr[KTOP - 1]) ins16(arr, p);
    }
#pragma unroll
    for (int s = 0; s < KTOP; s++) cand[s][tid] = arr[s];
    __syncthreads();

    for (int r = 0; r < MCAND; r++) {
        unsigned long long lm = ~0ull;
        int lp = -1;
#pragma unroll
        for (int s = 0; s < KTOP; s++) {
            unsigned long long v = cand[s][tid];
            if (v < lm) { lm = v; lp = s; }
        }
        red[tid] = lm;
        __syncthreads();
        for (int s = TPB / 2; s > 0; s >>= 1) {
            if (tid < s) {
                unsigned long long o = red[tid + s];
                if (o < red[tid]) red[tid] = o;
            }
            __syncthreads();
        }
        unsigned long long g = red[0];
        if (lm == g && lp >= 0) cand[lp][tid] = ~0ull;   // unique owner
        if (tid == 0) g_cand[q * MCAND + r] = g;
        __syncthreads();
    }
}

// ---- Pass R: reference-replica rescore + top-16 + compositing -------------
// One 64-thread CTA per query. Each thread owns one candidate and replicates
// the reference's fp32 arithmetic EXACTLY (same op sequence, same association,
// sequential-d single-accumulator FMA chains matching gemm k-order):
//   iv   = fl(exp(-lv))
//   q2   = sum_d fma(fl(q*q), iv)       cross = sum_d fma(q, fl(mu*iv))
//   m2   = sum_d add( fl(fl(mu*mu)*iv) )
//   mahal= fl(fl(q2 - fl(2*cross)) + m2)
//   score= fl( fl(exp( fl( fl(-0.5*mahal) / tau ) )) * alpha )
// Ranking by (score desc, index asc) == jax.lax.top_k semantics.
__global__ void __launch_bounds__(MCAND) refine_kernel(
    const float* __restrict__ query, const float* __restrict__ mu,
    const float* __restrict__ log_var, const float* __restrict__ raw_alpha,
    const float* __restrict__ features, const float* __restrict__ log_tau,
    float* __restrict__ out, int B, int DF, int write_tres)
{
    __shared__ float smu[MCAND][DS + 1];
    __shared__ float slv[MCAND][DS + 1];
    __shared__ float sq[DS];
    __shared__ int   scid[MCAND];
    __shared__ unsigned long long skey[MCAND];
    __shared__ int   ssel[KTOP];       // candidate slot per rank
    __shared__ float smah[KTOP];
    __shared__ float sw_[KTOP];
    __shared__ float stres;

    const int q = blockIdx.x;
    const int t = threadIdx.x;         // 0..63

    sq[t]   = query[(size_t)q * DS + t];
    scid[t] = (int)(g_cand[q * MCAND + t] & 0xffffffffull);
    __syncthreads();

    // cooperative, coalesced load of candidate rows
    for (int c = 0; c < MCAND; c++) {
        int id = scid[c];
        smu[c][t] = mu[(size_t)id * DS + t];
        slv[c][t] = log_var[(size_t)id * DS + t];
    }
    __syncthreads();

    const float tau = expf(log_tau[0]);

    // --- replicate reference score for candidate t ---
    float q2 = 0.f, cross = 0.f, m2 = 0.f;
    for (int d = 0; d < DS; d++) {
        float lv  = slv[t][d];
        float iv  = expf(-lv);
        float m   = smu[t][d];
        float miv = m * iv;            // elementwise fl(mu*inv_var)
        float qq  = sq[d] * sq[d];     // elementwise fl(q*q)
        q2    = fmaf(qq,    iv,  q2);  // sequential-k FMA chain (gemm order)
        cross = fmaf(sq[d], miv, cross);
        m2    = m2 + (m * m) * iv;     // elementwise product then add-reduce
    }
    float mahal = (q2 - 2.0f * cross) + m2;
    float K     = expf((-0.5f * mahal) / tau);
    float a     = 1.0f / (1.0f + expf(-raw_alpha[scid[t]]));
    float score = K * a;
    skey[t] = packdesc(score, scid[t]);
    __syncthreads();

    // rank by counting (keys unique: index embedded)
    {
        unsigned long long mk = skey[t];
        int rank = 0;
#pragma unroll 8
        for (int j = 0; j < MCAND; j++) rank += (skey[j] < mk);
        if (rank < KTOP) ssel[rank] = t;
    }
    __syncthreads();

    // exact diff-form mahalanobis for the chosen 16 (reference render path)
    if (t < KTOP) {
        int c = ssel[t];
        float s = 0.f;
        for (int d = 0; d < DS; d++) {
            float df = sq[d] - smu[c][d];
            s = s + (df * df) * expf(-slv[c][d]);
        }
        smah[t] = s;
    }
    __syncthreads();

    if (t == 0) {
        const float tk = (float)(0.3 / 16.0);   // T_MAX / k
        float cum = 0.f;
        for (int j = 0; j < KTOP; j++) {
            int   c   = ssel[j];
            float Kv  = expf((-0.5f * smah[j]) / tau);
            float al  = 1.0f / (1.0f + expf(-raw_alpha[scid[c]]));
            float eff = fminf(al * Kv, tk);
            sw_[j] = eff * expf(cum);           // log_T before update
            cum   += log1pf(-fminf(eff, 1.0f - 1e-6f));
        }
        stres = expf(cum);
    }
    __syncthreads();

    for (int d = t; d < DF; d += MCAND) {
        float acc = 0.f;
#pragma unroll
        for (int j = 0; j < KTOP; j++) {
            int id = scid[ssel[j]];
            acc += sw_[j] * features[(size_t)id * DF + d];
        }
        out[(size_t)q * DF + d] = acc;
    }
    if (t == 0 && write_tres) out[(size_t)B * DF + q] = stres;
}

// ---- launch ---------------------------------------------------------------
extern "C" void kernel_launch(void* const* d_in, const int* in_sizes, int n_in,
                              void* d_out, int out_size)
{
    const float* query     = (const float*)d_in[0];
    const float* mu        = (const float*)d_in[1];
    const float* log_var   = (const float*)d_in[2];
    const float* raw_alpha = (const float*)d_in[3];
    const float* features  = (const float*)d_in[4];
    const float* log_tau   = (const float*)d_in[5];

    const int N  = in_sizes[3];            // 131072
    const int B  = in_sizes[0] / DS;       // 1024
    const int DF = in_sizes[4] / N;        // 256
    float* out = (float*)d_out;
    const int write_tres = (out_size >= B * DF + B) ? 1 : 0;

    prep_kernel<<<N / 32, TPB>>>(mu, log_var, raw_alpha, log_tau, N);
    score_kernel<<<dim3(NCHUNK, B / QT), TPB>>>(query, N);
    topk_kernel<<<B, TPB>>>(N);
    refine_kernel<<<B, MCAND>>>(query, mu, log_var, raw_alpha, features,
                                log_tau, out, B, DF, write_tres);
}